// round 1
// baseline (speedup 1.0000x reference)
#include <cuda_runtime.h>
#include <math.h>

#define BB 256
#define TT 512
#define HH 1024
#define OO 256

// Double-buffered hidden state across step launches (2 MB static, allowed).
__device__ float g_h[2][BB * HH];

__device__ __forceinline__ unsigned long long fma2(unsigned long long a,
                                                   unsigned long long b,
                                                   unsigned long long c) {
    unsigned long long d;
    asm("fma.rn.f32x2 %0, %1, %2, %3;" : "=l"(d) : "l"(a), "l"(b), "l"(c));
    return d;
}

// t = 0: h = tanh(x[:,0] * W_x + b_ih)   (h0 is zero, so no h @ W_h term)
__global__ __launch_bounds__(256) void step0_kernel(
    const float* __restrict__ x,
    const float* __restrict__ W_ih,
    const float* __restrict__ b_ih) {
    int j = (blockIdx.x & 3) * 256 + threadIdx.x;
    int b = blockIdx.x >> 2;
    float v = tanhf(x[b * TT + 0] * W_ih[j] + b_ih[j]);  // W_ih row 0 = W_x
    g_h[1][b * HH + j] = v;
}

// One recurrence step: h_out = tanh(x[:,t] W_x + h_in @ W_h + b_ih)
// CTA tile: 32 rows (b) x 64 cols (j), K = 1024 in chunks of 32.
// Thread tile: 2 rows x 4 cols, accumulators packed as f32x2 column pairs.
__global__ __launch_bounds__(256) void step_kernel(
    const float* __restrict__ x,
    const float* __restrict__ W_ih,
    const float* __restrict__ b_ih,
    int t, int rd) {
    const float* __restrict__ h_in = g_h[rd];
    float* __restrict__ h_out = g_h[rd ^ 1];

    __shared__ __align__(16) float ws[2][32][64];  // W_h chunk [k][j]
    __shared__ __align__(16) float hs[2][32][66];  // h chunk, duplicated: [k][2b]=(v), [2b+1]=(v); pad 66

    const int tid = threadIdx.x;
    const int tx = tid & 15;   // col group: 4 cols
    const int ty = tid >> 4;   // row group: 2 rows
    const int b0 = blockIdx.y * 32;
    const int j0 = blockIdx.x * 64;

    // staging roles
    const int kw = tid >> 3;   // 0..31 : W row within chunk
    const int jq = tid & 7;    // 0..7  : 8 floats of j per thread
    const int bh = tid >> 3;   // 0..31 : h row
    const int kq = tid & 7;    // 0..7  : 4 k per thread

    unsigned long long a00 = 0ull, a01 = 0ull, a10 = 0ull, a11 = 0ull;

    float4 hreg, w0reg, w1reg;
    // prologue: load + store chunk 0
    hreg  = *(const float4*)(h_in + (b0 + bh) * HH + kq * 4);
    {
        const float* wp = W_ih + (1 + kw) * HH + j0 + jq * 8;
        w0reg = *(const float4*)wp;
        w1reg = *(const float4*)(wp + 4);
    }
    *(float4*)&ws[0][kw][jq * 8]     = w0reg;
    *(float4*)&ws[0][kw][jq * 8 + 4] = w1reg;
    {
        const float* hv = &hreg.x;
        #pragma unroll
        for (int i = 0; i < 4; ++i) {
            float v = hv[i];
            *(float2*)&hs[0][kq * 4 + i][2 * bh] = make_float2(v, v);
        }
    }
    __syncthreads();

    #pragma unroll 1
    for (int c = 0; c < 32; ++c) {
        const int buf = c & 1;
        // prefetch next chunk (global -> regs), overlapped with compute
        if (c + 1 < 32) {
            hreg = *(const float4*)(h_in + (b0 + bh) * HH + (c + 1) * 32 + kq * 4);
            const float* wp = W_ih + (1 + (c + 1) * 32 + kw) * HH + j0 + jq * 8;
            w0reg = *(const float4*)wp;
            w1reg = *(const float4*)(wp + 4);
        }
        #pragma unroll
        for (int k = 0; k < 32; ++k) {
            unsigned long long hv0 = *(const unsigned long long*)&hs[buf][k][4 * ty];
            unsigned long long hv1 = *(const unsigned long long*)&hs[buf][k][4 * ty + 2];
            const unsigned long long* wp2 =
                (const unsigned long long*)&ws[buf][k][4 * tx];
            unsigned long long w01 = wp2[0];
            unsigned long long w23 = wp2[1];
            a00 = fma2(hv0, w01, a00);
            a01 = fma2(hv0, w23, a01);
            a10 = fma2(hv1, w01, a10);
            a11 = fma2(hv1, w23, a11);
        }
        if (c + 1 < 32) {
            const int nbuf = buf ^ 1;
            *(float4*)&ws[nbuf][kw][jq * 8]     = w0reg;
            *(float4*)&ws[nbuf][kw][jq * 8 + 4] = w1reg;
            const float* hv = &hreg.x;
            #pragma unroll
            for (int i = 0; i < 4; ++i) {
                float v = hv[i];
                *(float2*)&hs[nbuf][kq * 4 + i][2 * bh] = make_float2(v, v);
            }
            __syncthreads();
        }
    }

    // epilogue: + x_t * W_x + bias, tanh, store
    const int r0 = b0 + 2 * ty;
    const int r1 = r0 + 1;
    const int jj = j0 + 4 * tx;
    const float xb0 = x[r0 * TT + t];
    const float xb1 = x[r1 * TT + t];
    const float4 wx = *(const float4*)(W_ih + jj);   // row 0
    const float4 bb = *(const float4*)(b_ih + jj);

    union U { unsigned long long u; float2 f; };
    U u00, u01, u10, u11;
    u00.u = a00; u01.u = a01; u10.u = a10; u11.u = a11;

    float4 o0, o1;
    o0.x = tanhf(u00.f.x + xb0 * wx.x + bb.x);
    o0.y = tanhf(u00.f.y + xb0 * wx.y + bb.y);
    o0.z = tanhf(u01.f.x + xb0 * wx.z + bb.z);
    o0.w = tanhf(u01.f.y + xb0 * wx.w + bb.w);
    o1.x = tanhf(u10.f.x + xb1 * wx.x + bb.x);
    o1.y = tanhf(u10.f.y + xb1 * wx.y + bb.y);
    o1.z = tanhf(u11.f.x + xb1 * wx.z + bb.z);
    o1.w = tanhf(u11.f.y + xb1 * wx.w + bb.w);

    *(float4*)(h_out + r0 * HH + jj) = o0;
    *(float4*)(h_out + r1 * HH + jj) = o1;
}

// out = h_final @ W_ho + b_ho ; h_final lives in g_h[0].
// One CTA per 2 batch rows; thread o in [0,256).
__global__ __launch_bounds__(256) void out_kernel(
    const float* __restrict__ W_ho,
    const float* __restrict__ b_ho,
    float* __restrict__ out) {
    __shared__ __align__(16) float hsm[2 * HH];
    const int b0 = blockIdx.x * 2;
    const float4* src = (const float4*)(&g_h[0][b0 * HH]);
    float4* dst = (float4*)hsm;
    dst[threadIdx.x]       = src[threadIdx.x];
    dst[threadIdx.x + 256] = src[threadIdx.x + 256];
    __syncthreads();

    const int o = threadIdx.x;
    float a0 = 0.f, a1 = 0.f;
    #pragma unroll 16
    for (int k = 0; k < HH; ++k) {
        float w = W_ho[k * OO + o];
        a0 += hsm[k] * w;
        a1 += hsm[HH + k] * w;
    }
    out[b0 * OO + o]       = a0 + b_ho[o];
    out[(b0 + 1) * OO + o] = a1 + b_ho[o];
}

extern "C" void kernel_launch(void* const* d_in, const int* in_sizes, int n_in,
                              void* d_out, int out_size) {
    const float* x    = (const float*)d_in[0];
    const float* W_ih = (const float*)d_in[1];
    const float* b_ih = (const float*)d_in[2];
    const float* W_ho = (const float*)d_in[3];
    const float* b_ho = (const float*)d_in[4];
    float* out = (float*)d_out;

    step0_kernel<<<BB * 4, 256>>>(x, W_ih, b_ih);
    for (int t = 1; t < TT; ++t) {
        step_kernel<<<dim3(16, 8), 256>>>(x, W_ih, b_ih, t, t & 1);
    }
    // final h is in g_h[0] (t=511 reads g_h[1], writes g_h[0])
    out_kernel<<<BB / 2, 256>>>(W_ho, b_ho, out);
}

// round 2
// speedup vs baseline: 1.1606x; 1.1606x over previous
#include <cuda_runtime.h>
#include <math.h>

#define BB 256
#define TT 512
#define HH 1024
#define OO 256

typedef unsigned long long u64;

// Double-buffered hidden state across step launches (2 MB static, allowed).
__device__ float g_h[2][BB * HH];

__device__ __forceinline__ u64 fma2(u64 a, u64 b, u64 c) {
    u64 d;
    asm("fma.rn.f32x2 %0, %1, %2, %3;" : "=l"(d) : "l"(a), "l"(b), "l"(c));
    return d;
}

// t = 0: h = tanh(x[:,0] * W_x + b_ih)   (h0 is zero)
__global__ __launch_bounds__(256) void step0_kernel(
    const float* __restrict__ x,
    const float* __restrict__ W_ih,
    const float* __restrict__ b_ih) {
    int j = (blockIdx.x & 3) * 256 + threadIdx.x;
    int b = blockIdx.x >> 2;
    float v = tanhf(x[b * TT + 0] * W_ih[j] + b_ih[j]);
    g_h[1][b * HH + j] = v;
}

// One step: h_out = tanh(x[:,t] W_x + h_in @ W_h + b_ih)
// CTA tile 32 b x 64 j. 256 threads; warps 0-3 handle k in [0,512),
// warps 4-7 handle k in [512,1024); reduce via smem at the end.
// Thread tile: 2 b-rows x 8 j-cols over its K half; accs are f32x2 j-pairs.
__global__ __launch_bounds__(256) void step_kernel(
    const float* __restrict__ x,
    const float* __restrict__ W_ih,
    const float* __restrict__ b_ih,
    int t, int rd) {
    const float* __restrict__ h_in = g_h[rd];
    float* __restrict__ h_out = g_h[rd ^ 1];

    // rows padded to 68 floats (272 B = 17x16B): keeps LDS.128 alignment,
    // breaks 128B-stride staging conflicts.
    __shared__ __align__(16) float ws[2][32][68];  // W chunk: rows 0-15 half0 k, 16-31 half1 k
    __shared__ __align__(16) float hs[2][32][68];  // h chunk, dup-packed + rotated

    const int tid  = threadIdx.x;
    const int half = tid >> 7;      // K half
    const int hid  = tid & 127;
    const int tx   = hid & 7;       // j: cols {4tx..4tx+3} and {32+4tx..+3}
    const int ty   = hid >> 3;      // b: rows 2ty, 2ty+1
    const int b0   = blockIdx.y * 32;
    const int j0   = blockIdx.x * 64;

    // staging roles
    const int wk  = tid >> 3;       // 0..31: W row within chunk
    const int wj4 = tid & 7;        // 8 floats of j
    const int hb  = tid >> 3;       // 0..31: h row (b)
    const int hk4 = tid & 7;        // group of 4 k within chunk

    // chunk-row -> global k base (add cc*16 each chunk)
    const int wk_kbase = (wk < 16) ? wk : (512 - 16 + wk);
    const float* wgp = W_ih + (size_t)(1 + wk_kbase) * HH + j0 + 8 * wj4;
    const int hk_kbase = (hk4 < 4) ? hk4 * 4 : (512 - 16 + hk4 * 4);
    const float* hgp = h_in + (size_t)(b0 + hb) * HH + hk_kbase;

    // rotated h column offsets (compute side), and fixed store column (staging)
    int hoff[8];
    #pragma unroll
    for (int r = 0; r < 8; ++r) hoff[r] = (4 * ty + 8 * r) & 63;
    const int hscol = (2 * hb + 8 * hk4) & 63;   // rot for store = kk>>2 = hk4 (fixed)

    // ---- stage chunk 0 ----
    {
        float4 w0 = *(const float4*)(wgp);
        float4 w1 = *(const float4*)(wgp + 4);
        *(float4*)&ws[0][wk][8 * wj4]     = w0;
        *(float4*)&ws[0][wk][8 * wj4 + 4] = w1;
        float4 hv = *(const float4*)(hgp);
        const float* hf = &hv.x;
        #pragma unroll
        for (int i = 0; i < 4; ++i) {
            float v = hf[i];
            *(float2*)&hs[0][hk4 * 4 + i][hscol] = make_float2(v, v);
        }
    }
    __syncthreads();

    u64 a0[4] = {0ull, 0ull, 0ull, 0ull};
    u64 a1[4] = {0ull, 0ull, 0ull, 0ull};

    #pragma unroll 1
    for (int cc = 0; cc < 32; ++cc) {
        const int buf = cc & 1;
        float4 w0r, w1r, hvr;
        if (cc < 31) {  // prefetch next chunk into regs
            const float* wp = wgp + (size_t)(cc + 1) * 16 * HH;
            w0r = *(const float4*)(wp);
            w1r = *(const float4*)(wp + 4);
            hvr = *(const float4*)(hgp + (cc + 1) * 16);
        }
        const float* hsb = &hs[buf][half * 16][0];
        const float* wsb = &ws[buf][half * 16][0];
        #pragma unroll
        for (int kk = 0; kk < 16; ++kk) {
            const int rot = ((half * 16 + kk) >> 2) & 7;
            ulonglong2 hv = *(const ulonglong2*)(hsb + kk * 68 + hoff[rot]);
            ulonglong2 wA = *(const ulonglong2*)(wsb + kk * 68 + 4 * tx);
            ulonglong2 wB = *(const ulonglong2*)(wsb + kk * 68 + 32 + 4 * tx);
            a0[0] = fma2(hv.x, wA.x, a0[0]);
            a0[1] = fma2(hv.x, wA.y, a0[1]);
            a0[2] = fma2(hv.x, wB.x, a0[2]);
            a0[3] = fma2(hv.x, wB.y, a0[3]);
            a1[0] = fma2(hv.y, wA.x, a1[0]);
            a1[1] = fma2(hv.y, wA.y, a1[1]);
            a1[2] = fma2(hv.y, wB.x, a1[2]);
            a1[3] = fma2(hv.y, wB.y, a1[3]);
        }
        if (cc < 31) {
            const int nb = buf ^ 1;
            *(float4*)&ws[nb][wk][8 * wj4]     = w0r;
            *(float4*)&ws[nb][wk][8 * wj4 + 4] = w1r;
            const float* hf = &hvr.x;
            #pragma unroll
            for (int i = 0; i < 4; ++i) {
                float v = hf[i];
                *(float2*)&hs[nb][hk4 * 4 + i][hscol] = make_float2(v, v);
            }
            __syncthreads();
        }
    }

    // ---- cross-half reduction + epilogue ----
    __syncthreads();  // everyone done reading smem; reuse hs as scratch
    float* scratch = &hs[0][0][0];
    if (half == 1) {
        ulonglong2* p = (ulonglong2*)(scratch + hid * 16);
        ulonglong2 v;
        v.x = a0[0]; v.y = a0[1]; p[0] = v;
        v.x = a0[2]; v.y = a0[3]; p[1] = v;
        v.x = a1[0]; v.y = a1[1]; p[2] = v;
        v.x = a1[2]; v.y = a1[3]; p[3] = v;
    }
    __syncthreads();
    if (half == 0) {
        const float* q = scratch + hid * 16;
        union U { u64 u; float2 f; };
        float s0[8], s1[8];
        #pragma unroll
        for (int p = 0; p < 4; ++p) {
            U u; u.u = a0[p];
            s0[2 * p]     = u.f.x + q[2 * p];
            s0[2 * p + 1] = u.f.y + q[2 * p + 1];
            u.u = a1[p];
            s1[2 * p]     = u.f.x + q[8 + 2 * p];
            s1[2 * p + 1] = u.f.y + q[8 + 2 * p + 1];
        }
        const int r0 = b0 + 2 * ty;
        const int r1 = r0 + 1;
        const int jA = j0 + 4 * tx;
        const int jB = jA + 32;
        const float xb0 = x[r0 * TT + t];
        const float xb1 = x[r1 * TT + t];
        const float4 wxA = *(const float4*)(W_ih + jA);
        const float4 wxB = *(const float4*)(W_ih + jB);
        const float4 bA  = *(const float4*)(b_ih + jA);
        const float4 bB  = *(const float4*)(b_ih + jB);

        float4 oA0, oB0, oA1, oB1;
        oA0.x = tanhf(s0[0] + xb0 * wxA.x + bA.x);
        oA0.y = tanhf(s0[1] + xb0 * wxA.y + bA.y);
        oA0.z = tanhf(s0[2] + xb0 * wxA.z + bA.z);
        oA0.w = tanhf(s0[3] + xb0 * wxA.w + bA.w);
        oB0.x = tanhf(s0[4] + xb0 * wxB.x + bB.x);
        oB0.y = tanhf(s0[5] + xb0 * wxB.y + bB.y);
        oB0.z = tanhf(s0[6] + xb0 * wxB.z + bB.z);
        oB0.w = tanhf(s0[7] + xb0 * wxB.w + bB.w);
        oA1.x = tanhf(s1[0] + xb1 * wxA.x + bA.x);
        oA1.y = tanhf(s1[1] + xb1 * wxA.y + bA.y);
        oA1.z = tanhf(s1[2] + xb1 * wxA.z + bA.z);
        oA1.w = tanhf(s1[3] + xb1 * wxA.w + bA.w);
        oB1.x = tanhf(s1[4] + xb1 * wxB.x + bB.x);
        oB1.y = tanhf(s1[5] + xb1 * wxB.y + bB.y);
        oB1.z = tanhf(s1[6] + xb1 * wxB.z + bB.z);
        oB1.w = tanhf(s1[7] + xb1 * wxB.w + bB.w);

        *(float4*)(h_out + (size_t)r0 * HH + jA) = oA0;
        *(float4*)(h_out + (size_t)r0 * HH + jB) = oB0;
        *(float4*)(h_out + (size_t)r1 * HH + jA) = oA1;
        *(float4*)(h_out + (size_t)r1 * HH + jB) = oB1;
    }
}

// out = h_final @ W_ho + b_ho ; h_final lives in g_h[0].
__global__ __launch_bounds__(256) void out_kernel(
    const float* __restrict__ W_ho,
    const float* __restrict__ b_ho,
    float* __restrict__ out) {
    __shared__ __align__(16) float hsm[2 * HH];
    const int b0 = blockIdx.x * 2;
    const float4* src = (const float4*)(&g_h[0][b0 * HH]);
    float4* dst = (float4*)hsm;
    dst[threadIdx.x]       = src[threadIdx.x];
    dst[threadIdx.x + 256] = src[threadIdx.x + 256];
    __syncthreads();

    const int o = threadIdx.x;
    float a0 = 0.f, a1 = 0.f;
    #pragma unroll 16
    for (int k = 0; k < HH; ++k) {
        float w = W_ho[k * OO + o];
        a0 += hsm[k] * w;
        a1 += hsm[HH + k] * w;
    }
    out[b0 * OO + o]       = a0 + b_ho[o];
    out[(b0 + 1) * OO + o] = a1 + b_ho[o];
}

extern "C" void kernel_launch(void* const* d_in, const int* in_sizes, int n_in,
                              void* d_out, int out_size) {
    const float* x    = (const float*)d_in[0];
    const float* W_ih = (const float*)d_in[1];
    const float* b_ih = (const float*)d_in[2];
    const float* W_ho = (const float*)d_in[3];
    const float* b_ho = (const float*)d_in[4];
    float* out = (float*)d_out;

    step0_kernel<<<BB * 4, 256>>>(x, W_ih, b_ih);
    for (int t = 1; t < TT; ++t) {
        step_kernel<<<dim3(16, 8), 256>>>(x, W_ih, b_ih, t, t & 1);
    }
    out_kernel<<<BB / 2, 256>>>(W_ho, b_ho, out);
}

// round 4
// speedup vs baseline: 3.1034x; 2.6740x over previous
#include <cuda_runtime.h>
#include <cuda_bf16.h>
#include <math.h>
#include <stdint.h>

#define BB 256
#define TT 512
#define HH 1024
#define OO 256

#define CK 64                 // K per chunk (bf16)
#define NCHUNK (HH / CK)      // 16
#define ROWB 144              // padded row stride in bytes (128 data + 16 pad)
#define A_HALF (32 * ROWB)    // 4608
#define B_HALF (64 * ROWB)    // 9216
#define STAGE_B (2 * A_HALF + 2 * B_HALF)   // 27648
#define STAGES 3
#define SMEM_TOTAL (STAGES * STAGE_B + 512) // 83456

__device__ __align__(1024) __nv_bfloat16 g_h_hi[2][BB * HH];
__device__ __align__(1024) __nv_bfloat16 g_h_lo[2][BB * HH];
__device__ __align__(1024) __nv_bfloat16 g_Wt_hi[HH * HH];
__device__ __align__(1024) __nv_bfloat16 g_Wt_lo[HH * HH];

// ---------- PTX helpers (sm_80-generic only) ----------
__device__ __forceinline__ uint32_t smem_u32(const void* p) {
    uint32_t a;
    asm("{ .reg .u64 t; cvta.to.shared.u64 t, %1; cvt.u32.u64 %0, t; }" : "=r"(a) : "l"(p));
    return a;
}
__device__ __forceinline__ void cp16(uint32_t d, const void* s) {
    asm volatile("cp.async.cg.shared.global [%0], [%1], 16;" :: "r"(d), "l"(s) : "memory");
}
#define CP_COMMIT() asm volatile("cp.async.commit_group;" ::: "memory")
#define CP_WAIT1()  asm volatile("cp.async.wait_group 1;" ::: "memory")

__device__ __forceinline__ void ldsm4(uint32_t* r, uint32_t a) {
    asm volatile("ldmatrix.sync.aligned.m8n8.x4.shared.b16 {%0,%1,%2,%3}, [%4];"
                 : "=r"(r[0]), "=r"(r[1]), "=r"(r[2]), "=r"(r[3]) : "r"(a));
}
__device__ __forceinline__ void mma16816(float* c, const uint32_t* a,
                                         uint32_t b0, uint32_t b1) {
    asm volatile(
        "mma.sync.aligned.m16n8k16.row.col.f32.bf16.bf16.f32 "
        "{%0,%1,%2,%3},{%4,%5,%6,%7},{%8,%9},{%0,%1,%2,%3};"
        : "+f"(c[0]), "+f"(c[1]), "+f"(c[2]), "+f"(c[3])
        : "r"(a[0]), "r"(a[1]), "r"(a[2]), "r"(a[3]), "r"(b0), "r"(b1));
}

// ---------- kernels ----------

// One-time: Wt_hi/lo[j][k] = split(W_ih[1+k][j])
__global__ __launch_bounds__(256) void wsplit_kernel(const float* __restrict__ W_ih) {
    __shared__ float tile[32][33];
    const int k0 = blockIdx.x * 32;
    const int j0 = blockIdx.y * 32;
    const int tx = threadIdx.x & 31;
    const int ty = threadIdx.x >> 5;
    #pragma unroll
    for (int i = 0; i < 4; ++i) {
        int k = ty + i * 8;
        tile[k][tx] = W_ih[(size_t)(1 + k0 + k) * HH + j0 + tx];
    }
    __syncthreads();
    #pragma unroll
    for (int i = 0; i < 4; ++i) {
        int j = ty + i * 8;
        float v = tile[tx][j];
        __nv_bfloat16 hi = __float2bfloat16(v);
        float lo = v - __bfloat162float(hi);
        g_Wt_hi[(size_t)(j0 + j) * HH + k0 + tx] = hi;
        g_Wt_lo[(size_t)(j0 + j) * HH + k0 + tx] = __float2bfloat16(lo);
    }
}

// t = 0: h = tanh(x[:,0]*Wx + b) -> split into buffer 1
__global__ __launch_bounds__(256) void step0_kernel(
    const float* __restrict__ x, const float* __restrict__ W_ih,
    const float* __restrict__ b_ih) {
    int j = (blockIdx.x & 3) * 256 + threadIdx.x;
    int b = blockIdx.x >> 2;
    float v = tanhf(x[b * TT] * W_ih[j] + b_ih[j]);
    __nv_bfloat16 hi = __float2bfloat16(v);
    g_h_hi[1][b * HH + j] = hi;
    g_h_lo[1][b * HH + j] = __float2bfloat16(v - __bfloat162float(hi));
}

// One step: h_out = tanh(x[:,t]*Wx + h_in @ W_h + b)
// CTA tile 32(b) x 64(j); warp tile 16x16 (warp_m = wid&1, warp_n = wid>>1).
// K = 1024 in 16 chunks of 64; 3 products hi*hi + hi*lo + lo*hi.
__global__ __launch_bounds__(256, 1) void mma_step(
    const float* __restrict__ x,
    const float* __restrict__ W_ih,
    const float* __restrict__ b_ih,
    int t, int rd) {
    extern __shared__ __align__(1024) char smem[];
    const uint32_t sb = smem_u32(smem);
    float* wx_s = (float*)(smem + STAGES * STAGE_B);
    float* bi_s = wx_s + 64;

    const int tid = threadIdx.x;
    const int wid = tid >> 5;
    const int lane = tid & 31;
    const int j0 = blockIdx.x * 64;
    const int m0 = blockIdx.y * 32;

    const __nv_bfloat16* __restrict__ hhi = g_h_hi[rd];
    const __nv_bfloat16* __restrict__ hlo = g_h_lo[rd];

    if (tid < 64) {
        wx_s[tid] = W_ih[j0 + tid];
        bi_s[tid] = b_ih[j0 + tid];
    }

    // cp.async source pointers for this thread (advance 64 elems per chunk)
    const int lr = tid >> 3;          // 0..31
    const int lc = tid & 7;           // 0..7 (16B column)
    const __nv_bfloat16* sAh = hhi + (size_t)(m0 + lr) * HH + lc * 8;
    const __nv_bfloat16* sAl = hlo + (size_t)(m0 + lr) * HH + lc * 8;
    const __nv_bfloat16* sB0h = g_Wt_hi + (size_t)(j0 + lr) * HH + lc * 8;
    const __nv_bfloat16* sB1h = g_Wt_hi + (size_t)(j0 + lr + 32) * HH + lc * 8;
    const __nv_bfloat16* sB0l = g_Wt_lo + (size_t)(j0 + lr) * HH + lc * 8;
    const __nv_bfloat16* sB1l = g_Wt_lo + (size_t)(j0 + lr + 32) * HH + lc * 8;
    const uint32_t drow = lr * ROWB + lc * 16;

    // ldmatrix per-thread offsets
    const int warp_m = wid & 1;
    const int warp_n = wid >> 1;
    const uint32_t aoff = (warp_m * 16 + (lane & 7) + ((lane >> 3) & 1) * 8) * ROWB
                        + (lane >> 4) * 16;
    const uint32_t boff = (warp_n * 16 + (lane & 7) + (lane >> 4) * 8) * ROWB
                        + ((lane >> 3) & 1) * 16;

    // prologue: chunks 0,1
    #pragma unroll
    for (int c = 0; c < STAGES - 1; ++c) {
        const uint32_t st = sb + c * STAGE_B;
        const int ke = c * CK;
        cp16(st + drow, sAh + ke);
        cp16(st + A_HALF + drow, sAl + ke);
        cp16(st + 2 * A_HALF + drow, sB0h + ke);
        cp16(st + 2 * A_HALF + 32 * ROWB + drow, sB1h + ke);
        cp16(st + 2 * A_HALF + B_HALF + drow, sB0l + ke);
        cp16(st + 2 * A_HALF + B_HALF + 32 * ROWB + drow, sB1l + ke);
        CP_COMMIT();
    }

    float c0[4] = {0.f, 0.f, 0.f, 0.f};
    float c1[4] = {0.f, 0.f, 0.f, 0.f};

    int st_idx = 0;
    #pragma unroll 1
    for (int c = 0; c < NCHUNK; ++c) {
        CP_WAIT1();
        __syncthreads();
        // issue loads for chunk c+2 into the stage just freed
        if (c + 2 < NCHUNK) {
            int ns = st_idx + 2; if (ns >= STAGES) ns -= STAGES;
            const uint32_t st = sb + ns * STAGE_B;
            const int ke = (c + 2) * CK;
            cp16(st + drow, sAh + ke);
            cp16(st + A_HALF + drow, sAl + ke);
            cp16(st + 2 * A_HALF + drow, sB0h + ke);
            cp16(st + 2 * A_HALF + 32 * ROWB + drow, sB1h + ke);
            cp16(st + 2 * A_HALF + B_HALF + drow, sB0l + ke);
            cp16(st + 2 * A_HALF + B_HALF + 32 * ROWB + drow, sB1l + ke);
        }
        CP_COMMIT();

        const uint32_t stb = sb + st_idx * STAGE_B;
        #pragma unroll
        for (int kk = 0; kk < CK / 16; ++kk) {
            uint32_t ah[4], al[4], bh[4], bl[4];
            ldsm4(ah, stb + aoff + kk * 32);
            ldsm4(al, stb + A_HALF + aoff + kk * 32);
            ldsm4(bh, stb + 2 * A_HALF + boff + kk * 32);
            ldsm4(bl, stb + 2 * A_HALF + B_HALF + boff + kk * 32);
            mma16816(c0, ah, bh[0], bh[1]);
            mma16816(c1, ah, bh[2], bh[3]);
            mma16816(c0, ah, bl[0], bl[1]);
            mma16816(c1, ah, bl[2], bl[3]);
            mma16816(c0, al, bh[0], bh[1]);
            mma16816(c1, al, bh[2], bh[3]);
        }
        if (++st_idx == STAGES) st_idx = 0;
    }

    // epilogue
    const int r0 = m0 + warp_m * 16 + (lane >> 2);
    const int r1 = r0 + 8;
    const float xb0 = x[r0 * TT + t];
    const float xb1 = x[r1 * TT + t];
    __nv_bfloat16* ph = g_h_hi[rd ^ 1];
    __nv_bfloat16* pl = g_h_lo[rd ^ 1];

    #pragma unroll
    for (int n8 = 0; n8 < 2; ++n8) {
        const float* cc = n8 ? c1 : c0;
        const int cj = warp_n * 16 + n8 * 8 + (lane & 3) * 2;
        const float wxa = wx_s[cj], wxb = wx_s[cj + 1];
        const float bia = bi_s[cj], bib = bi_s[cj + 1];
        float v00 = tanhf(cc[0] + xb0 * wxa + bia);
        float v01 = tanhf(cc[1] + xb0 * wxb + bib);
        float v10 = tanhf(cc[2] + xb1 * wxa + bia);
        float v11 = tanhf(cc[3] + xb1 * wxb + bib);

        __nv_bfloat162 h0, l0, h1, l1;
        h0.x = __float2bfloat16(v00); h0.y = __float2bfloat16(v01);
        l0.x = __float2bfloat16(v00 - __bfloat162float(h0.x));
        l0.y = __float2bfloat16(v01 - __bfloat162float(h0.y));
        h1.x = __float2bfloat16(v10); h1.y = __float2bfloat16(v11);
        l1.x = __float2bfloat16(v10 - __bfloat162float(h1.x));
        l1.y = __float2bfloat16(v11 - __bfloat162float(h1.y));

        const size_t o0 = (size_t)r0 * HH + j0 + cj;
        const size_t o1 = (size_t)r1 * HH + j0 + cj;
        *(uint32_t*)(ph + o0) = *(uint32_t*)&h0;
        *(uint32_t*)(pl + o0) = *(uint32_t*)&l0;
        *(uint32_t*)(ph + o1) = *(uint32_t*)&h1;
        *(uint32_t*)(pl + o1) = *(uint32_t*)&l1;
    }
}

// out = h_final @ W_ho + b_ho ; h_final = hi+lo in buffer 0
__global__ __launch_bounds__(256) void out_kernel(
    const float* __restrict__ W_ho, const float* __restrict__ b_ho,
    float* __restrict__ out) {
    __shared__ __align__(16) float hsm[2 * HH];
    const int b0 = blockIdx.x * 2;
    const __nv_bfloat16* sh = &g_h_hi[0][(size_t)b0 * HH];
    const __nv_bfloat16* sl = &g_h_lo[0][(size_t)b0 * HH];
    for (int i = threadIdx.x; i < 2 * HH; i += 256)
        hsm[i] = __bfloat162float(sh[i]) + __bfloat162float(sl[i]);
    __syncthreads();

    const int o = threadIdx.x;
    float a0 = 0.f, a1 = 0.f;
    #pragma unroll 16
    for (int k = 0; k < HH; ++k) {
        float w = W_ho[k * OO + o];
        a0 += hsm[k] * w;
        a1 += hsm[HH + k] * w;
    }
    out[b0 * OO + o]       = a0 + b_ho[o];
    out[(b0 + 1) * OO + o] = a1 + b_ho[o];
}

extern "C" void kernel_launch(void* const* d_in, const int* in_sizes, int n_in,
                              void* d_out, int out_size) {
    const float* x    = (const float*)d_in[0];
    const float* W_ih = (const float*)d_in[1];
    const float* b_ih = (const float*)d_in[2];
    const float* W_ho = (const float*)d_in[3];
    const float* b_ho = (const float*)d_in[4];
    float* out = (float*)d_out;

    static int smem_set = 0;
    if (!smem_set) {
        cudaFuncSetAttribute(mma_step, cudaFuncAttributeMaxDynamicSharedMemorySize,
                             SMEM_TOTAL);
        smem_set = 1;
    }

    wsplit_kernel<<<dim3(32, 32), 256>>>(W_ih);
    step0_kernel<<<BB * 4, 256>>>(x, W_ih, b_ih);
    for (int t = 1; t < TT; ++t) {
        mma_step<<<dim3(16, 8), 256, SMEM_TOTAL>>>(x, W_ih, b_ih, t, t & 1);
    }
    out_kernel<<<BB / 2, 256>>>(W_ho, b_ho, out);
}